// round 9
// baseline (speedup 1.0000x reference)
#include <cuda_runtime.h>
#include <cuda_bf16.h>

#define NPATCH 8192
#define NTILES 128
#define NTOT   8320
#define NEDGES 1024
#define INDIM  384
#define DMODEL 256
#define NHEADS 4
#define DHEAD  64
#define MAXDEG 1024

// ---------------- scratch (static device globals; no allocation) ----------------
__device__ float g_hA[NTOT * DMODEL];           // post-GEMM h (fp32)
__device__ __nv_bfloat16 g_hAb[NTOT * DMODEL];  // bf16 copy for stage1 gathers
__device__ float g_hB[NTOT * DMODEL];           // post-layer h
__device__ float g_ssrc[NTOT * NHEADS];
__device__ float g_sdst[NTOT * NHEADS];
__device__ float g_sedg[NEDGES * NHEADS];
__device__ __nv_bfloat16 g_mb[NEDGES * DMODEL]; // bf16 edge messages for stage2 gathers
__device__ int   g_edge_mem[NEDGES * MAXDEG];
__device__ int   g_edge_cnt[NEDGES];
__device__ int   g_node_edges[NTOT * MAXDEG];
__device__ int   g_node_cnt[NTOT];

// ---------------- helpers ----------------
__device__ __forceinline__ float wsum(float v) {
#pragma unroll
    for (int o = 16; o; o >>= 1) v += __shfl_xor_sync(0xffffffffu, v, o);
    return v;
}
__device__ __forceinline__ float lrelu(float x) { return x >= 0.f ? x : 0.2f * x; }

__device__ __forceinline__ float2 bf2_to_f2(unsigned u) {
    float2 r;
    r.x = __uint_as_float(u << 16);
    r.y = __uint_as_float(u & 0xffff0000u);
    return r;
}

__device__ __forceinline__ void mma_bf16(float* c, const unsigned* a, const unsigned* b) {
    asm volatile(
        "mma.sync.aligned.m16n8k16.row.col.f32.bf16.bf16.f32 "
        "{%0,%1,%2,%3}, {%4,%5,%6,%7}, {%8,%9}, {%0,%1,%2,%3};\n"
        : "+f"(c[0]), "+f"(c[1]), "+f"(c[2]), "+f"(c[3])
        : "r"(a[0]), "r"(a[1]), "r"(a[2]), "r"(a[3]), "r"(b[0]), "r"(b[1]));
}

__device__ __forceinline__ void split_bf16(float v, __nv_bfloat16& hi, __nv_bfloat16& lo) {
    __nv_bfloat16 h = __float2bfloat16_rn(v);
    hi = h;
    lo = __float2bfloat16_rn(v - __bfloat162float(h));
}

// ---------------- adjacency build: fully warp-local ordered compaction (no barriers) ----
// Warps 0..255: CSC, 4 edge columns each (float4 reads). Warps 256..8575: CSR, 1 node row each.
// Ordering identical to the previous block-wide compaction -> bit-identical lists.
#define CSC_WARPS (NEDGES / 4)
__global__ __launch_bounds__(256) void build_kernel(const float* __restrict__ H) {
    const int gw = blockIdx.x * 8 + (threadIdx.x >> 5);
    const int lane = threadIdx.x & 31;
    if (gw < CSC_WARPS) {
        const int e0 = gw * 4;
        int b0 = 0, b1 = 0, b2 = 0, b3 = 0;
        for (int n0 = 0; n0 < NTOT; n0 += 32) {
            int n = n0 + lane;
            float4 v = *(const float4*)(H + (size_t)n * NEDGES + e0);
            unsigned m0 = __ballot_sync(0xffffffffu, v.x > 0.f);
            unsigned m1 = __ballot_sync(0xffffffffu, v.y > 0.f);
            unsigned m2 = __ballot_sync(0xffffffffu, v.z > 0.f);
            unsigned m3 = __ballot_sync(0xffffffffu, v.w > 0.f);
            unsigned lt = (1u << lane) - 1u;
            if (v.x > 0.f) { int p = b0 + __popc(m0 & lt); if (p < MAXDEG) g_edge_mem[(size_t)(e0 + 0) * MAXDEG + p] = n; }
            if (v.y > 0.f) { int p = b1 + __popc(m1 & lt); if (p < MAXDEG) g_edge_mem[(size_t)(e0 + 1) * MAXDEG + p] = n; }
            if (v.z > 0.f) { int p = b2 + __popc(m2 & lt); if (p < MAXDEG) g_edge_mem[(size_t)(e0 + 2) * MAXDEG + p] = n; }
            if (v.w > 0.f) { int p = b3 + __popc(m3 & lt); if (p < MAXDEG) g_edge_mem[(size_t)(e0 + 3) * MAXDEG + p] = n; }
            b0 += __popc(m0); b1 += __popc(m1); b2 += __popc(m2); b3 += __popc(m3);
        }
        if (lane == 0) {
            g_edge_cnt[e0 + 0] = b0 < MAXDEG ? b0 : MAXDEG;
            g_edge_cnt[e0 + 1] = b1 < MAXDEG ? b1 : MAXDEG;
            g_edge_cnt[e0 + 2] = b2 < MAXDEG ? b2 : MAXDEG;
            g_edge_cnt[e0 + 3] = b3 < MAXDEG ? b3 : MAXDEG;
        }
    } else {
        const int n = gw - CSC_WARPS;
        if (n >= NTOT) return;
        const float* row = H + (size_t)n * NEDGES;
        int* outp = g_node_edges + (size_t)n * MAXDEG;
        int base = 0;
        for (int e0 = 0; e0 < NEDGES; e0 += 32) {
            bool p = row[e0 + lane] > 0.f;
            unsigned b = __ballot_sync(0xffffffffu, p);
            if (p) outp[base + __popc(b & ((1u << lane) - 1u))] = e0 + lane;
            base += __popc(b);
        }
        if (lane == 0) g_node_cnt[n] = base;
    }
}

// ---------------- tensor-core GEMM (split-bf16) + fused s_src/s_dst epilogue ----------------
// BM=128, BN=128, BK=32 (R6 configuration — known good).
template <int KDIM, bool FIRST>
__global__ __launch_bounds__(256) void gemm_tc_kernel(
    const float* __restrict__ A, const float* __restrict__ RO,
    const float* __restrict__ W, const float* __restrict__ nemb,
    const int* __restrict__ ntype,
    const float* __restrict__ asrc, const float* __restrict__ adst) {
    constexpr int SA = 36;
    __shared__ __nv_bfloat16 sAhi[128 * SA];
    __shared__ __nv_bfloat16 sAlo[128 * SA];
    __shared__ __nv_bfloat16 sBhi[128 * SA];  // n-major: [n][k]
    __shared__ __nv_bfloat16 sBlo[128 * SA];

    const int m0 = blockIdx.x * 128, n0 = blockIdx.y * 128;
    const int tid = threadIdx.x, lane = tid & 31, warp = tid >> 5;
    const int g = lane >> 2, tg = lane & 3;
    const int wm = warp & 3, wn = warp >> 2;
    const float* Asrc = FIRST ? A : g_hB;

    float acc[2][8][4];
#pragma unroll
    for (int mt = 0; mt < 2; mt++)
#pragma unroll
        for (int nt = 0; nt < 8; nt++)
#pragma unroll
            for (int j = 0; j < 4; j++) acc[mt][nt][j] = 0.f;

    const int KT = KDIM / 32;
    for (int kt = 0; kt < KT; kt++) {
        const int k0 = kt * 32;
#pragma unroll
        for (int i = 0; i < 4; i++) {
            int idx = tid + i * 256;
            int r = idx >> 3, kc = (idx & 7) * 4;
            int grow = m0 + r;
            float4 v;
            if (FIRST && grow >= NPATCH) v = *(const float4*)(RO + k0 + kc);
            else v = *(const float4*)(Asrc + (size_t)grow * KDIM + k0 + kc);
            float vv[4] = {v.x, v.y, v.z, v.w};
#pragma unroll
            for (int j = 0; j < 4; j++) {
                __nv_bfloat16 hi, lo;
                split_bf16(vv[j], hi, lo);
                sAhi[r * SA + kc + j] = hi;
                sAlo[r * SA + kc + j] = lo;
            }
        }
#pragma unroll
        for (int i = 0; i < 4; i++) {
            int idx = tid + i * 256;
            int k = idx >> 5, nq = (idx & 31) * 4;
            float4 v = *(const float4*)(W + (size_t)(k0 + k) * DMODEL + n0 + nq);
            float vv[4] = {v.x, v.y, v.z, v.w};
#pragma unroll
            for (int j = 0; j < 4; j++) {
                __nv_bfloat16 hi, lo;
                split_bf16(vv[j], hi, lo);
                sBhi[(nq + j) * SA + k] = hi;
                sBlo[(nq + j) * SA + k] = lo;
            }
        }
        __syncthreads();

#pragma unroll
        for (int ks = 0; ks < 2; ks++) {
            const int kb = ks * 16;
            unsigned ahi[2][4], alo[2][4];
#pragma unroll
            for (int mt = 0; mt < 2; mt++) {
                int r0 = wm * 32 + mt * 16 + g;
                ahi[mt][0] = *(const unsigned*)&sAhi[r0 * SA + kb + 2 * tg];
                ahi[mt][1] = *(const unsigned*)&sAhi[(r0 + 8) * SA + kb + 2 * tg];
                ahi[mt][2] = *(const unsigned*)&sAhi[r0 * SA + kb + 2 * tg + 8];
                ahi[mt][3] = *(const unsigned*)&sAhi[(r0 + 8) * SA + kb + 2 * tg + 8];
                alo[mt][0] = *(const unsigned*)&sAlo[r0 * SA + kb + 2 * tg];
                alo[mt][1] = *(const unsigned*)&sAlo[(r0 + 8) * SA + kb + 2 * tg];
                alo[mt][2] = *(const unsigned*)&sAlo[r0 * SA + kb + 2 * tg + 8];
                alo[mt][3] = *(const unsigned*)&sAlo[(r0 + 8) * SA + kb + 2 * tg + 8];
            }
#pragma unroll
            for (int nt = 0; nt < 8; nt++) {
                int n = wn * 64 + nt * 8 + g;
                unsigned bhi[2], blo[2];
                bhi[0] = *(const unsigned*)&sBhi[n * SA + kb + 2 * tg];
                bhi[1] = *(const unsigned*)&sBhi[n * SA + kb + 2 * tg + 8];
                blo[0] = *(const unsigned*)&sBlo[n * SA + kb + 2 * tg];
                blo[1] = *(const unsigned*)&sBlo[n * SA + kb + 2 * tg + 8];
#pragma unroll
                for (int mt = 0; mt < 2; mt++) {
                    mma_bf16(acc[mt][nt], alo[mt], bhi);
                    mma_bf16(acc[mt][nt], ahi[mt], blo);
                    mma_bf16(acc[mt][nt], ahi[mt], bhi);
                }
            }
        }
        __syncthreads();
    }

    const int h = 2 * blockIdx.y + wn;
#pragma unroll
    for (int mt = 0; mt < 2; mt++) {
        int r_a = m0 + wm * 32 + mt * 16 + g;
        int r_b = r_a + 8;
        int ta = ntype[r_a], tb = ntype[r_b];
        float ssa = 0.f, ssb = 0.f, sda = 0.f, sdb = 0.f;
#pragma unroll
        for (int nt = 0; nt < 8; nt++) {
            int c = n0 + wn * 64 + nt * 8 + 2 * tg;
            int d = nt * 8 + 2 * tg;
            float v0 = acc[mt][nt][0] + nemb[ta * DMODEL + c];
            float v1 = acc[mt][nt][1] + nemb[ta * DMODEL + c + 1];
            float v2 = acc[mt][nt][2] + nemb[tb * DMODEL + c];
            float v3 = acc[mt][nt][3] + nemb[tb * DMODEL + c + 1];
            *(float2*)&g_hA[(size_t)r_a * DMODEL + c] = make_float2(v0, v1);
            *(float2*)&g_hA[(size_t)r_b * DMODEL + c] = make_float2(v2, v3);
            __nv_bfloat162 ba, bb;
            ba.x = __float2bfloat16_rn(v0); ba.y = __float2bfloat16_rn(v1);
            bb.x = __float2bfloat16_rn(v2); bb.y = __float2bfloat16_rn(v3);
            *(__nv_bfloat162*)&g_hAb[(size_t)r_a * DMODEL + c] = ba;
            *(__nv_bfloat162*)&g_hAb[(size_t)r_b * DMODEL + c] = bb;
            float as0 = asrc[h * DHEAD + d], as1 = asrc[h * DHEAD + d + 1];
            float ad0 = adst[h * DHEAD + d], ad1 = adst[h * DHEAD + d + 1];
            ssa += v0 * as0 + v1 * as1;
            ssb += v2 * as0 + v3 * as1;
            sda += v0 * ad0 + v1 * ad1;
            sdb += v2 * ad0 + v3 * ad1;
        }
#pragma unroll
        for (int o = 1; o <= 2; o <<= 1) {
            ssa += __shfl_xor_sync(0xffffffffu, ssa, o);
            ssb += __shfl_xor_sync(0xffffffffu, ssb, o);
            sda += __shfl_xor_sync(0xffffffffu, sda, o);
            sdb += __shfl_xor_sync(0xffffffffu, sdb, o);
        }
        if (tg == 0) {
            g_ssrc[r_a * NHEADS + h] = ssa;
            g_ssrc[r_b * NHEADS + h] = ssb;
            g_sdst[r_a * NHEADS + h] = sda;
            g_sdst[r_b * NHEADS + h] = sdb;
        }
    }
}

// ---------------- stage 1: node -> edge, single-pass, 8 cols/thread (R6 version) ----------------
__global__ void stage1_kernel(const float* __restrict__ ebias, const int* __restrict__ etype,
                              const float* __restrict__ aedg) {
    const int e = blockIdx.x;
    const int tid = threadIdx.x, lane = tid & 31, wid = tid >> 5;
    const int cnt = g_edge_cnt[e];
    __shared__ float s_eb[4], s_inv[4];
    __shared__ float s_red[8][4];
    __shared__ uint2 s_pairs[4 * 256];   // per head: (row offset in uint4 units, weight)
    __shared__ float s_part[8 * 256];
    if (tid < 4) s_eb[tid] = ebias[etype[e] * 4 + tid];
    __syncthreads();
    const int* mem = g_edge_mem + (size_t)e * MAXDEG;

    const int o = tid & 31;        // column oct: cols 8o..8o+7
    const int slice = tid >> 5;    // member slice 0..7
    const int hq = o >> 3;         // head of this oct
    const uint4* basep = (const uint4*)g_hAb + o;
    float a0 = 0.f, a1 = 0.f, a2 = 0.f, a3 = 0.f, a4 = 0.f, a5 = 0.f, a6 = 0.f, a7 = 0.f;
    float w0 = 0.f, w1 = 0.f, w2 = 0.f, w3 = 0.f;

    for (int base = 0; base < cnt; base += 256) {
        int i = base + tid;
        if (i < cnt) {
            int n = mem[i];
            unsigned off = (unsigned)n * (DMODEL / 8);
            float4 ss = *(const float4*)(g_ssrc + n * 4);
            float e0 = __expf(lrelu(ss.x + s_eb[0]));
            float e1 = __expf(lrelu(ss.y + s_eb[1]));
            float e2 = __expf(lrelu(ss.z + s_eb[2]));
            float e3 = __expf(lrelu(ss.w + s_eb[3]));
            s_pairs[0 * 256 + tid] = make_uint2(off, __float_as_uint(e0));
            s_pairs[1 * 256 + tid] = make_uint2(off, __float_as_uint(e1));
            s_pairs[2 * 256 + tid] = make_uint2(off, __float_as_uint(e2));
            s_pairs[3 * 256 + tid] = make_uint2(off, __float_as_uint(e3));
            w0 += e0; w1 += e1; w2 += e2; w3 += e3;
        }
        __syncthreads();
        int lim = min(256, cnt - base);
#pragma unroll 4
        for (int j = slice; j < lim; j += 8) {
            uint2 pw = s_pairs[hq * 256 + j];
            float a = __uint_as_float(pw.y);
            uint4 u = basep[pw.x];
            float2 c0 = bf2_to_f2(u.x), c1 = bf2_to_f2(u.y);
            float2 c2 = bf2_to_f2(u.z), c3 = bf2_to_f2(u.w);
            a0 += a * c0.x; a1 += a * c0.y; a2 += a * c1.x; a3 += a * c1.y;
            a4 += a * c2.x; a5 += a * c2.y; a6 += a * c3.x; a7 += a * c3.y;
        }
        __syncthreads();
    }

    w0 = wsum(w0); w1 = wsum(w1); w2 = wsum(w2); w3 = wsum(w3);
    if (lane == 0) { s_red[wid][0] = w0; s_red[wid][1] = w1; s_red[wid][2] = w2; s_red[wid][3] = w3; }
    float* pp = s_part + slice * 256 + o * 8;
    pp[0] = a0; pp[1] = a1; pp[2] = a2; pp[3] = a3;
    pp[4] = a4; pp[5] = a5; pp[6] = a6; pp[7] = a7;
    __syncthreads();
    if (tid < 4) {
        float t = 0.f;
        for (int w = 0; w < 8; w++) t += s_red[w][tid];
        s_inv[tid] = 1.f / t;
    }
    __syncthreads();
    const int c = tid;
    float m_c = 0.f;
#pragma unroll
    for (int s = 0; s < 8; s++) m_c += s_part[s * 256 + c];
    m_c *= s_inv[c >> 6];
    g_mb[(size_t)e * DMODEL + c] = __float2bfloat16_rn(m_c);

    float se = m_c * aedg[c];
    se = wsum(se);
    if (lane == 0) s_red[wid][0] = se;
    __syncthreads();
    if (tid < 4) g_sedg[e * 4 + tid] = s_red[2 * tid][0] + s_red[2 * tid + 1][0];
}

// ---------------- stage 2: edge -> node, single-pass, 8 cols/thread (R6 version) ----------------
__global__ void stage2_kernel() {
    const int n = blockIdx.x;
    const int tid = threadIdx.x, lane = tid & 31, wid = tid >> 5;
    const int cnt = g_node_cnt[n];
    __shared__ float s_sd[4], s_inv[4];
    __shared__ float s_red[8][4];
    __shared__ uint2 s_pairs[4 * 256];
    __shared__ float s_part[8 * 256];
    if (tid < 4) s_sd[tid] = g_sdst[n * 4 + tid];
    __syncthreads();
    const int* el = g_node_edges + (size_t)n * MAXDEG;

    const int o = tid & 31;
    const int slice = tid >> 5;
    const int hq = o >> 3;
    const uint4* basep = (const uint4*)g_mb + o;
    float a0 = 0.f, a1 = 0.f, a2 = 0.f, a3 = 0.f, a4 = 0.f, a5 = 0.f, a6 = 0.f, a7 = 0.f;
    float w0 = 0.f, w1 = 0.f, w2 = 0.f, w3 = 0.f;

    for (int base = 0; base < cnt; base += 256) {
        int i = base + tid;
        if (i < cnt) {
            int e = el[i];
            unsigned off = (unsigned)e * (DMODEL / 8);
            float4 sg = *(const float4*)(g_sedg + e * 4);
            float e0 = __expf(lrelu(s_sd[0] + sg.x));
            float e1 = __expf(lrelu(s_sd[1] + sg.y));
            float e2 = __expf(lrelu(s_sd[2] + sg.z));
            float e3 = __expf(lrelu(s_sd[3] + sg.w));
            s_pairs[0 * 256 + tid] = make_uint2(off, __float_as_uint(e0));
            s_pairs[1 * 256 + tid] = make_uint2(off, __float_as_uint(e1));
            s_pairs[2 * 256 + tid] = make_uint2(off, __float_as_uint(e2));
            s_pairs[3 * 256 + tid] = make_uint2(off, __float_as_uint(e3));
            w0 += e0; w1 += e1; w2 += e2; w3 += e3;
        }
        __syncthreads();
        int lim = min(256, cnt - base);
#pragma unroll 4
        for (int j = slice; j < lim; j += 8) {
            uint2 pw = s_pairs[hq * 256 + j];
            float b = __uint_as_float(pw.y);
            uint4 u = basep[pw.x];
            float2 c0 = bf2_to_f2(u.x), c1 = bf2_to_f2(u.y);
            float2 c2 = bf2_to_f2(u.z), c3 = bf2_to_f2(u.w);
            a0 += b * c0.x; a1 += b * c0.y; a2 += b * c1.x; a3 += b * c1.y;
            a4 += b * c2.x; a5 += b * c2.y; a6 += b * c3.x; a7 += b * c3.y;
        }
        __syncthreads();
    }

    w0 = wsum(w0); w1 = wsum(w1); w2 = wsum(w2); w3 = wsum(w3);
    if (lane == 0) { s_red[wid][0] = w0; s_red[wid][1] = w1; s_red[wid][2] = w2; s_red[wid][3] = w3; }
    float* pp = s_part + slice * 256 + o * 8;
    pp[0] = a0; pp[1] = a1; pp[2] = a2; pp[3] = a3;
    pp[4] = a4; pp[5] = a5; pp[6] = a6; pp[7] = a7;
    __syncthreads();
    if (tid < 4) {
        float t = 0.f;
        for (int w = 0; w < 8; w++) t += s_red[w][tid];
        s_inv[tid] = 1.f / t;
    }
    __syncthreads();
    const int c = tid;
    float acc = 0.f;
#pragma unroll
    for (int s = 0; s < 8; s++) acc += s_part[s * 256 + c];
    acc *= s_inv[c >> 6];
    float o2 = acc > 0.f ? acc : (__expf(acc) - 1.f);       // ELU(alpha=1)
    g_hB[(size_t)n * DMODEL + c] = o2 + g_hA[(size_t)n * DMODEL + c];
}

// ---------------- final layer norm ----------------
__global__ void ln_kernel(const float* __restrict__ ng, const float* __restrict__ nb,
                          const float* __restrict__ bg, const float* __restrict__ bb,
                          float* __restrict__ out) {
    const int n = blockIdx.x;
    const int tid = threadIdx.x, lane = tid & 31, wid = tid >> 5;
    __shared__ float sred[8];
    __shared__ float s_mean, s_rstd;
    float x = g_hB[(size_t)n * DMODEL + tid];
    float s = wsum(x);
    if (lane == 0) sred[wid] = s;
    __syncthreads();
    if (tid == 0) {
        float t = 0.f;
        for (int w = 0; w < 8; w++) t += sred[w];
        s_mean = t * (1.f / DMODEL);
    }
    __syncthreads();
    float c = x - s_mean;
    float v = wsum(c * c);
    if (lane == 0) sred[wid] = v;
    __syncthreads();
    if (tid == 0) {
        float t = 0.f;
        for (int w = 0; w < 8; w++) t += sred[w];
        s_rstd = rsqrtf(t * (1.f / DMODEL) + 1e-5f);
    }
    __syncthreads();
    const float* g = (n < NPATCH) ? ng : bg;
    const float* b = (n < NPATCH) ? nb : bb;
    out[(size_t)n * DMODEL + tid] = c * s_rstd * g[tid] + b[tid];
}

// ---------------- launcher ----------------
extern "C" void kernel_launch(void* const* d_in, const int* in_sizes, int n_in,
                              void* d_out, int out_size) {
    const float* x_nodes = (const float*)d_in[0];
    const float* ro      = (const float*)d_in[1];
    const int*   ntype   = (const int*)d_in[2];
    const int*   etype   = (const int*)d_in[3];
    const float* H       = (const float*)d_in[4];
    // d_in[5] readout_node_ids == arange(8192, 8320)
    const float* W0      = (const float*)d_in[6];
    const float* W1      = (const float*)d_in[7];
    const float* nemb    = (const float*)d_in[8];
    const float* asrc    = (const float*)d_in[9];
    const float* adst    = (const float*)d_in[10];
    const float* aedg    = (const float*)d_in[11];
    const float* ebias   = (const float*)d_in[12];
    const float* ngam    = (const float*)d_in[13];
    const float* nbet    = (const float*)d_in[14];
    const float* bgam    = (const float*)d_in[15];
    const float* bbet    = (const float*)d_in[16];
    float* out = (float*)d_out;

    // stage2 (layer 0) stays at our #3 = profiled slot (reversion check: expect ~40us)
    const int build_warps = CSC_WARPS + NTOT;
    build_kernel<<<(build_warps + 7) / 8, 256>>>(H);                            // #0
    gemm_tc_kernel<INDIM, true><<<dim3(NTOT / 128, DMODEL / 128), 256>>>(
        x_nodes, ro, W0, nemb + 0 * 4 * DMODEL, ntype, asrc, adst);             // #1
    stage1_kernel<<<NEDGES, 256>>>(ebias, etype, aedg);                         // #2
    stage2_kernel<<<NTOT, 256>>>();                                             // #3 (profiled)

    gemm_tc_kernel<DMODEL, false><<<dim3(NTOT / 128, DMODEL / 128), 256>>>(
        nullptr, nullptr, W1, nemb + 1 * 4 * DMODEL, ntype,
        asrc + NHEADS * DHEAD, adst + NHEADS * DHEAD);                          // #4
    stage1_kernel<<<NEDGES, 256>>>(ebias + 3 * NHEADS, etype, aedg + NHEADS * DHEAD);
    stage2_kernel<<<NTOT, 256>>>();

    ln_kernel<<<NTOT, 256>>>(ngam, nbet, bgam, bbet, out);
}

// round 10
// speedup vs baseline: 1.2228x; 1.2228x over previous
#include <cuda_runtime.h>
#include <cuda_bf16.h>

#define NPATCH 8192
#define NTILES 128
#define NTOT   8320
#define NEDGES 1024
#define INDIM  384
#define DMODEL 256
#define NHEADS 4
#define DHEAD  64
#define MAXDEG 1024

// ---------------- scratch (static device globals; no allocation) ----------------
__device__ float g_hA[NTOT * DMODEL];           // post-GEMM h (fp32)
__device__ __nv_bfloat16 g_hAb[NTOT * DMODEL];  // bf16 copy for stage1 gathers
__device__ float g_hB[NTOT * DMODEL];           // post-layer h
__device__ float g_ssrc[NTOT * NHEADS];
__device__ float g_sdst[NTOT * NHEADS];
__device__ float g_sedg[NEDGES * NHEADS];
__device__ __nv_bfloat16 g_mb[NEDGES * DMODEL]; // bf16 edge messages for stage2 gathers
__device__ int   g_edge_mem[NEDGES * MAXDEG];
__device__ int   g_edge_cnt[NEDGES];
__device__ int   g_node_edges[NTOT * MAXDEG];
__device__ int   g_node_cnt[NTOT];

// ---------------- helpers ----------------
__device__ __forceinline__ float wsum(float v) {
#pragma unroll
    for (int o = 16; o; o >>= 1) v += __shfl_xor_sync(0xffffffffu, v, o);
    return v;
}
__device__ __forceinline__ float lrelu(float x) { return x >= 0.f ? x : 0.2f * x; }

__device__ __forceinline__ float2 bf2_to_f2(unsigned u) {
    float2 r;
    r.x = __uint_as_float(u << 16);
    r.y = __uint_as_float(u & 0xffff0000u);
    return r;
}

__device__ __forceinline__ void mma_bf16(float* c, const unsigned* a, const unsigned* b) {
    asm volatile(
        "mma.sync.aligned.m16n8k16.row.col.f32.bf16.bf16.f32 "
        "{%0,%1,%2,%3}, {%4,%5,%6,%7}, {%8,%9}, {%0,%1,%2,%3};\n"
        : "+f"(c[0]), "+f"(c[1]), "+f"(c[2]), "+f"(c[3])
        : "r"(a[0]), "r"(a[1]), "r"(a[2]), "r"(a[3]), "r"(b[0]), "r"(b[1]));
}

__device__ __forceinline__ void split_bf16(float v, __nv_bfloat16& hi, __nv_bfloat16& lo) {
    __nv_bfloat16 h = __float2bfloat16_rn(v);
    hi = h;
    lo = __float2bfloat16_rn(v - __bfloat162float(h));
}

// ---------------- CSC build: 4 edges per block via float4 (R6 block version) ----------------
__global__ void build_csc_kernel(const float* __restrict__ H) {
    const int e0 = blockIdx.x * 4;
    const int tid = threadIdx.x, lane = tid & 31, wid = tid >> 5;
    __shared__ int s_base[4];
    __shared__ int s_wcnt[8][4];
    if (tid < 4) s_base[tid] = 0;
    __syncthreads();
    for (int base = 0; base < NTOT; base += 256) {
        int n = base + tid;
        float4 v = make_float4(0.f, 0.f, 0.f, 0.f);
        if (n < NTOT) v = *(const float4*)(H + (size_t)n * NEDGES + e0);
        bool p[4] = {v.x > 0.f, v.y > 0.f, v.z > 0.f, v.w > 0.f};
        unsigned b[4];
#pragma unroll
        for (int j = 0; j < 4; j++) b[j] = __ballot_sync(0xffffffffu, p[j]);
        if (lane == 0) {
#pragma unroll
            for (int j = 0; j < 4; j++) s_wcnt[wid][j] = __popc(b[j]);
        }
        __syncthreads();
#pragma unroll
        for (int j = 0; j < 4; j++) {
            if (p[j]) {
                int woff = 0;
                for (int w = 0; w < wid; w++) woff += s_wcnt[w][j];
                int pos = s_base[j] + woff + __popc(b[j] & ((1u << lane) - 1u));
                if (pos < MAXDEG) g_edge_mem[(size_t)(e0 + j) * MAXDEG + pos] = n;
            }
        }
        __syncthreads();
        if (tid < 4) {
            int tot = 0;
            for (int w = 0; w < 8; w++) tot += s_wcnt[w][tid];
            s_base[tid] += tot;
        }
        __syncthreads();
    }
    if (tid < 4) g_edge_cnt[e0 + tid] = s_base[tid] < MAXDEG ? s_base[tid] : MAXDEG;
}

// ---------------- CSR build: one block per node (R6 block version) ----------------
__global__ void build_csr_kernel(const float* __restrict__ H) {
    const int n = blockIdx.x;
    const int tid = threadIdx.x, lane = tid & 31, wid = tid >> 5;
    const float* row = H + (size_t)n * NEDGES;
    __shared__ int s_base;
    __shared__ int s_wcnt[8];
    if (tid == 0) s_base = 0;
    __syncthreads();
    for (int base = 0; base < NEDGES; base += 256) {
        int e = base + tid;
        bool p = row[e] > 0.f;
        unsigned b = __ballot_sync(0xffffffffu, p);
        if (lane == 0) s_wcnt[wid] = __popc(b);
        __syncthreads();
        int woff = 0;
        for (int w = 0; w < wid; w++) woff += s_wcnt[w];
        if (p) {
            int pos = s_base + woff + __popc(b & ((1u << lane) - 1u));
            g_node_edges[(size_t)n * MAXDEG + pos] = e;
        }
        __syncthreads();
        if (tid == 0) {
            int tot = 0;
            for (int w = 0; w < 8; w++) tot += s_wcnt[w];
            s_base += tot;
        }
        __syncthreads();
    }
    if (tid == 0) g_node_cnt[n] = s_base;
}

// ---------------- tensor-core GEMM (split-bf16) + fused s_src/s_dst epilogue ----------------
// BM=128, BN=128, BK=32 (R6 configuration — known good).
template <int KDIM, bool FIRST>
__global__ __launch_bounds__(256) void gemm_tc_kernel(
    const float* __restrict__ A, const float* __restrict__ RO,
    const float* __restrict__ W, const float* __restrict__ nemb,
    const int* __restrict__ ntype,
    const float* __restrict__ asrc, const float* __restrict__ adst) {
    constexpr int SA = 36;
    __shared__ __nv_bfloat16 sAhi[128 * SA];
    __shared__ __nv_bfloat16 sAlo[128 * SA];
    __shared__ __nv_bfloat16 sBhi[128 * SA];  // n-major: [n][k]
    __shared__ __nv_bfloat16 sBlo[128 * SA];

    const int m0 = blockIdx.x * 128, n0 = blockIdx.y * 128;
    const int tid = threadIdx.x, lane = tid & 31, warp = tid >> 5;
    const int g = lane >> 2, tg = lane & 3;
    const int wm = warp & 3, wn = warp >> 2;
    const float* Asrc = FIRST ? A : g_hB;

    float acc[2][8][4];
#pragma unroll
    for (int mt = 0; mt < 2; mt++)
#pragma unroll
        for (int nt = 0; nt < 8; nt++)
#pragma unroll
            for (int j = 0; j < 4; j++) acc[mt][nt][j] = 0.f;

    const int KT = KDIM / 32;
    for (int kt = 0; kt < KT; kt++) {
        const int k0 = kt * 32;
#pragma unroll
        for (int i = 0; i < 4; i++) {
            int idx = tid + i * 256;
            int r = idx >> 3, kc = (idx & 7) * 4;
            int grow = m0 + r;
            float4 v;
            if (FIRST && grow >= NPATCH) v = *(const float4*)(RO + k0 + kc);
            else v = *(const float4*)(Asrc + (size_t)grow * KDIM + k0 + kc);
            float vv[4] = {v.x, v.y, v.z, v.w};
#pragma unroll
            for (int j = 0; j < 4; j++) {
                __nv_bfloat16 hi, lo;
                split_bf16(vv[j], hi, lo);
                sAhi[r * SA + kc + j] = hi;
                sAlo[r * SA + kc + j] = lo;
            }
        }
#pragma unroll
        for (int i = 0; i < 4; i++) {
            int idx = tid + i * 256;
            int k = idx >> 5, nq = (idx & 31) * 4;
            float4 v = *(const float4*)(W + (size_t)(k0 + k) * DMODEL + n0 + nq);
            float vv[4] = {v.x, v.y, v.z, v.w};
#pragma unroll
            for (int j = 0; j < 4; j++) {
                __nv_bfloat16 hi, lo;
                split_bf16(vv[j], hi, lo);
                sBhi[(nq + j) * SA + k] = hi;
                sBlo[(nq + j) * SA + k] = lo;
            }
        }
        __syncthreads();

#pragma unroll
        for (int ks = 0; ks < 2; ks++) {
            const int kb = ks * 16;
            unsigned ahi[2][4], alo[2][4];
#pragma unroll
            for (int mt = 0; mt < 2; mt++) {
                int r0 = wm * 32 + mt * 16 + g;
                ahi[mt][0] = *(const unsigned*)&sAhi[r0 * SA + kb + 2 * tg];
                ahi[mt][1] = *(const unsigned*)&sAhi[(r0 + 8) * SA + kb + 2 * tg];
                ahi[mt][2] = *(const unsigned*)&sAhi[r0 * SA + kb + 2 * tg + 8];
                ahi[mt][3] = *(const unsigned*)&sAhi[(r0 + 8) * SA + kb + 2 * tg + 8];
                alo[mt][0] = *(const unsigned*)&sAlo[r0 * SA + kb + 2 * tg];
                alo[mt][1] = *(const unsigned*)&sAlo[(r0 + 8) * SA + kb + 2 * tg];
                alo[mt][2] = *(const unsigned*)&sAlo[r0 * SA + kb + 2 * tg + 8];
                alo[mt][3] = *(const unsigned*)&sAlo[(r0 + 8) * SA + kb + 2 * tg + 8];
            }
#pragma unroll
            for (int nt = 0; nt < 8; nt++) {
                int n = wn * 64 + nt * 8 + g;
                unsigned bhi[2], blo[2];
                bhi[0] = *(const unsigned*)&sBhi[n * SA + kb + 2 * tg];
                bhi[1] = *(const unsigned*)&sBhi[n * SA + kb + 2 * tg + 8];
                blo[0] = *(const unsigned*)&sBlo[n * SA + kb + 2 * tg];
                blo[1] = *(const unsigned*)&sBlo[n * SA + kb + 2 * tg + 8];
#pragma unroll
                for (int mt = 0; mt < 2; mt++) {
                    mma_bf16(acc[mt][nt], alo[mt], bhi);
                    mma_bf16(acc[mt][nt], ahi[mt], blo);
                    mma_bf16(acc[mt][nt], ahi[mt], bhi);
                }
            }
        }
        __syncthreads();
    }

    const int h = 2 * blockIdx.y + wn;
#pragma unroll
    for (int mt = 0; mt < 2; mt++) {
        int r_a = m0 + wm * 32 + mt * 16 + g;
        int r_b = r_a + 8;
        int ta = ntype[r_a], tb = ntype[r_b];
        float ssa = 0.f, ssb = 0.f, sda = 0.f, sdb = 0.f;
#pragma unroll
        for (int nt = 0; nt < 8; nt++) {
            int c = n0 + wn * 64 + nt * 8 + 2 * tg;
            int d = nt * 8 + 2 * tg;
            float v0 = acc[mt][nt][0] + nemb[ta * DMODEL + c];
            float v1 = acc[mt][nt][1] + nemb[ta * DMODEL + c + 1];
            float v2 = acc[mt][nt][2] + nemb[tb * DMODEL + c];
            float v3 = acc[mt][nt][3] + nemb[tb * DMODEL + c + 1];
            *(float2*)&g_hA[(size_t)r_a * DMODEL + c] = make_float2(v0, v1);
            *(float2*)&g_hA[(size_t)r_b * DMODEL + c] = make_float2(v2, v3);
            __nv_bfloat162 ba, bb;
            ba.x = __float2bfloat16_rn(v0); ba.y = __float2bfloat16_rn(v1);
            bb.x = __float2bfloat16_rn(v2); bb.y = __float2bfloat16_rn(v3);
            *(__nv_bfloat162*)&g_hAb[(size_t)r_a * DMODEL + c] = ba;
            *(__nv_bfloat162*)&g_hAb[(size_t)r_b * DMODEL + c] = bb;
            float as0 = asrc[h * DHEAD + d], as1 = asrc[h * DHEAD + d + 1];
            float ad0 = adst[h * DHEAD + d], ad1 = adst[h * DHEAD + d + 1];
            ssa += v0 * as0 + v1 * as1;
            ssb += v2 * as0 + v3 * as1;
            sda += v0 * ad0 + v1 * ad1;
            sdb += v2 * ad0 + v3 * ad1;
        }
#pragma unroll
        for (int o = 1; o <= 2; o <<= 1) {
            ssa += __shfl_xor_sync(0xffffffffu, ssa, o);
            ssb += __shfl_xor_sync(0xffffffffu, ssb, o);
            sda += __shfl_xor_sync(0xffffffffu, sda, o);
            sdb += __shfl_xor_sync(0xffffffffu, sdb, o);
        }
        if (tg == 0) {
            g_ssrc[r_a * NHEADS + h] = ssa;
            g_ssrc[r_b * NHEADS + h] = ssb;
            g_sdst[r_a * NHEADS + h] = sda;
            g_sdst[r_b * NHEADS + h] = sdb;
        }
    }
}

// ---------------- stage 1: node -> edge, single-pass, 8 cols/thread (R6 version) ----------------
__global__ void stage1_kernel(const float* __restrict__ ebias, const int* __restrict__ etype,
                              const float* __restrict__ aedg) {
    const int e = blockIdx.x;
    const int tid = threadIdx.x, lane = tid & 31, wid = tid >> 5;
    const int cnt = g_edge_cnt[e];
    __shared__ float s_eb[4], s_inv[4];
    __shared__ float s_red[8][4];
    __shared__ uint2 s_pairs[4 * 256];   // per head: (row offset in uint4 units, weight)
    __shared__ float s_part[8 * 256];
    if (tid < 4) s_eb[tid] = ebias[etype[e] * 4 + tid];
    __syncthreads();
    const int* mem = g_edge_mem + (size_t)e * MAXDEG;

    const int o = tid & 31;        // column oct: cols 8o..8o+7
    const int slice = tid >> 5;    // member slice 0..7
    const int hq = o >> 3;         // head of this oct
    const uint4* basep = (const uint4*)g_hAb + o;
    float a0 = 0.f, a1 = 0.f, a2 = 0.f, a3 = 0.f, a4 = 0.f, a5 = 0.f, a6 = 0.f, a7 = 0.f;
    float w0 = 0.f, w1 = 0.f, w2 = 0.f, w3 = 0.f;

    for (int base = 0; base < cnt; base += 256) {
        int i = base + tid;
        if (i < cnt) {
            int n = mem[i];
            unsigned off = (unsigned)n * (DMODEL / 8);
            float4 ss = *(const float4*)(g_ssrc + n * 4);
            float e0 = __expf(lrelu(ss.x + s_eb[0]));
            float e1 = __expf(lrelu(ss.y + s_eb[1]));
            float e2 = __expf(lrelu(ss.z + s_eb[2]));
            float e3 = __expf(lrelu(ss.w + s_eb[3]));
            s_pairs[0 * 256 + tid] = make_uint2(off, __float_as_uint(e0));
            s_pairs[1 * 256 + tid] = make_uint2(off, __float_as_uint(e1));
            s_pairs[2 * 256 + tid] = make_uint2(off, __float_as_uint(e2));
            s_pairs[3 * 256 + tid] = make_uint2(off, __float_as_uint(e3));
            w0 += e0; w1 += e1; w2 += e2; w3 += e3;
        }
        __syncthreads();
        int lim = min(256, cnt - base);
#pragma unroll 4
        for (int j = slice; j < lim; j += 8) {
            uint2 pw = s_pairs[hq * 256 + j];
            float a = __uint_as_float(pw.y);
            uint4 u = basep[pw.x];
            float2 c0 = bf2_to_f2(u.x), c1 = bf2_to_f2(u.y);
            float2 c2 = bf2_to_f2(u.z), c3 = bf2_to_f2(u.w);
            a0 += a * c0.x; a1 += a * c0.y; a2 += a * c1.x; a3 += a * c1.y;
            a4 += a * c2.x; a5 += a * c2.y; a6 += a * c3.x; a7 += a * c3.y;
        }
        __syncthreads();
    }

    w0 = wsum(w0); w1 = wsum(w1); w2 = wsum(w2); w3 = wsum(w3);
    if (lane == 0) { s_red[wid][0] = w0; s_red[wid][1] = w1; s_red[wid][2] = w2; s_red[wid][3] = w3; }
    float* pp = s_part + slice * 256 + o * 8;
    pp[0] = a0; pp[1] = a1; pp[2] = a2; pp[3] = a3;
    pp[4] = a4; pp[5] = a5; pp[6] = a6; pp[7] = a7;
    __syncthreads();
    if (tid < 4) {
        float t = 0.f;
        for (int w = 0; w < 8; w++) t += s_red[w][tid];
        s_inv[tid] = 1.f / t;
    }
    __syncthreads();
    const int c = tid;
    float m_c = 0.f;
#pragma unroll
    for (int s = 0; s < 8; s++) m_c += s_part[s * 256 + c];
    m_c *= s_inv[c >> 6];
    g_mb[(size_t)e * DMODEL + c] = __float2bfloat16_rn(m_c);

    float se = m_c * aedg[c];
    se = wsum(se);
    if (lane == 0) s_red[wid][0] = se;
    __syncthreads();
    if (tid < 4) g_sedg[e * 4 + tid] = s_red[2 * tid][0] + s_red[2 * tid + 1][0];
}

// ---------------- stage 2: edge -> node (R6 version) + optional fused final LayerNorm ----------
template <bool LAST>
__global__ void stage2_kernel(const float* __restrict__ ng, const float* __restrict__ nb,
                              const float* __restrict__ bg, const float* __restrict__ bb,
                              float* __restrict__ out) {
    const int n = blockIdx.x;
    const int tid = threadIdx.x, lane = tid & 31, wid = tid >> 5;
    const int cnt = g_node_cnt[n];
    __shared__ float s_sd[4], s_inv[4];
    __shared__ float s_red[8][4];
    __shared__ uint2 s_pairs[4 * 256];
    __shared__ float s_part[8 * 256];
    if (tid < 4) s_sd[tid] = g_sdst[n * 4 + tid];
    __syncthreads();
    const int* el = g_node_edges + (size_t)n * MAXDEG;

    const int o = tid & 31;
    const int slice = tid >> 5;
    const int hq = o >> 3;
    const uint4* basep = (const uint4*)g_mb + o;
    float a0 = 0.f, a1 = 0.f, a2 = 0.f, a3 = 0.f, a4 = 0.f, a5 = 0.f, a6 = 0.f, a7 = 0.f;
    float w0 = 0.f, w1 = 0.f, w2 = 0.f, w3 = 0.f;

    for (int base = 0; base < cnt; base += 256) {
        int i = base + tid;
        if (i < cnt) {
            int e = el[i];
            unsigned off = (unsigned)e * (DMODEL / 8);
            float4 sg = *(const float4*)(g_sedg + e * 4);
            float e0 = __expf(lrelu(s_sd[0] + sg.x));
            float e1 = __expf(lrelu(s_sd[1] + sg.y));
            float e2 = __expf(lrelu(s_sd[2] + sg.z));
            float e3 = __expf(lrelu(s_sd[3] + sg.w));
            s_pairs[0 * 256 + tid] = make_uint2(off, __float_as_uint(e0));
            s_pairs[1 * 256 + tid] = make_uint2(off, __float_as_uint(e1));
            s_pairs[2 * 256 + tid] = make_uint2(off, __float_as_uint(e2));
            s_pairs[3 * 256 + tid] = make_uint2(off, __float_as_uint(e3));
            w0 += e0; w1 += e1; w2 += e2; w3 += e3;
        }
        __syncthreads();
        int lim = min(256, cnt - base);
#pragma unroll 4
        for (int j = slice; j < lim; j += 8) {
            uint2 pw = s_pairs[hq * 256 + j];
            float b = __uint_as_float(pw.y);
            uint4 u = basep[pw.x];
            float2 c0 = bf2_to_f2(u.x), c1 = bf2_to_f2(u.y);
            float2 c2 = bf2_to_f2(u.z), c3 = bf2_to_f2(u.w);
            a0 += b * c0.x; a1 += b * c0.y; a2 += b * c1.x; a3 += b * c1.y;
            a4 += b * c2.x; a5 += b * c2.y; a6 += b * c3.x; a7 += b * c3.y;
        }
        __syncthreads();
    }

    w0 = wsum(w0); w1 = wsum(w1); w2 = wsum(w2); w3 = wsum(w3);
    if (lane == 0) { s_red[wid][0] = w0; s_red[wid][1] = w1; s_red[wid][2] = w2; s_red[wid][3] = w3; }
    float* pp = s_part + slice * 256 + o * 8;
    pp[0] = a0; pp[1] = a1; pp[2] = a2; pp[3] = a3;
    pp[4] = a4; pp[5] = a5; pp[6] = a6; pp[7] = a7;
    __syncthreads();
    if (tid < 4) {
        float t = 0.f;
        for (int w = 0; w < 8; w++) t += s_red[w][tid];
        s_inv[tid] = 1.f / t;
    }
    __syncthreads();
    const int c = tid;
    float acc = 0.f;
#pragma unroll
    for (int s = 0; s < 8; s++) acc += s_part[s * 256 + c];
    acc *= s_inv[c >> 6];
    float o2 = acc > 0.f ? acc : (__expf(acc) - 1.f);       // ELU(alpha=1)
    float x = o2 + g_hA[(size_t)n * DMODEL + c];

    if (!LAST) {
        g_hB[(size_t)n * DMODEL + c] = x;
    } else {
        // fused final LayerNorm (identical reduction structure to the old ln_kernel)
        __shared__ float sred[8];
        __shared__ float s_mean, s_rstd;
        float s = wsum(x);
        if (lane == 0) sred[wid] = s;
        __syncthreads();
        if (tid == 0) {
            float t = 0.f;
            for (int w = 0; w < 8; w++) t += sred[w];
            s_mean = t * (1.f / DMODEL);
        }
        __syncthreads();
        float cc = x - s_mean;
        float v = wsum(cc * cc);
        if (lane == 0) sred[wid] = v;
        __syncthreads();
        if (tid == 0) {
            float t = 0.f;
            for (int w = 0; w < 8; w++) t += sred[w];
            s_rstd = rsqrtf(t * (1.f / DMODEL) + 1e-5f);
        }
        __syncthreads();
        const float* gg = (n < NPATCH) ? ng : bg;
        const float* bbp = (n < NPATCH) ? nb : bb;
        out[(size_t)n * DMODEL + c] = cc * s_rstd * gg[c] + bbp[c];
    }
}

// ---------------- launcher ----------------
extern "C" void kernel_launch(void* const* d_in, const int* in_sizes, int n_in,
                              void* d_out, int out_size) {
    const float* x_nodes = (const float*)d_in[0];
    const float* ro      = (const float*)d_in[1];
    const int*   ntype   = (const int*)d_in[2];
    const int*   etype   = (const int*)d_in[3];
    const float* H       = (const float*)d_in[4];
    // d_in[5] readout_node_ids == arange(8192, 8320)
    const float* W0      = (const float*)d_in[6];
    const float* W1      = (const float*)d_in[7];
    const float* nemb    = (const float*)d_in[8];
    const float* asrc    = (const float*)d_in[9];
    const float* adst    = (const float*)d_in[10];
    const float* aedg    = (const float*)d_in[11];
    const float* ebias   = (const float*)d_in[12];
    const float* ngam    = (const float*)d_in[13];
    const float* nbet    = (const float*)d_in[14];
    const float* bgam    = (const float*)d_in[15];
    const float* bbet    = (const float*)d_in[16];
    float* out = (float*)d_out;

    // order: stage1 (layer 0) sits at our #3 = ncu's profiled launch slot
    build_csc_kernel<<<NEDGES / 4, 256>>>(H);                                   // #0
    build_csr_kernel<<<NTOT, 256>>>(H);                                         // #1
    gemm_tc_kernel<INDIM, true><<<dim3(NTOT / 128, DMODEL / 128), 256>>>(
        x_nodes, ro, W0, nemb + 0 * 4 * DMODEL, ntype, asrc, adst);             // #2
    stage1_kernel<<<NEDGES, 256>>>(ebias, etype, aedg);                         // #3 (profiled)
    stage2_kernel<false><<<NTOT, 256>>>(nullptr, nullptr, nullptr, nullptr, nullptr); // #4

    gemm_tc_kernel<DMODEL, false><<<dim3(NTOT / 128, DMODEL / 128), 256>>>(
        nullptr, nullptr, W1, nemb + 1 * 4 * DMODEL, ntype,
        asrc + NHEADS * DHEAD, adst + NHEADS * DHEAD);                          // #5
    stage1_kernel<<<NEDGES, 256>>>(ebias + 3 * NHEADS, etype, aedg + NHEADS * DHEAD); // #6
    stage2_kernel<true><<<NTOT, 256>>>(ngam, nbet, bgam, bbet, out);            // #7
}

// round 11
// speedup vs baseline: 1.3644x; 1.1158x over previous
#include <cuda_runtime.h>
#include <cuda_bf16.h>

#define NPATCH 8192
#define NTILES 128
#define NTOT   8320
#define NEDGES 1024
#define INDIM  384
#define DMODEL 256
#define NHEADS 4
#define DHEAD  64
#define MAXDEG 1024

// ---------------- scratch (static device globals; no allocation) ----------------
__device__ float g_hA[NTOT * DMODEL];           // post-GEMM h (fp32)
__device__ __nv_bfloat16 g_hAb[NTOT * DMODEL];  // bf16 copy for stage1 gathers
__device__ float g_hB[NTOT * DMODEL];           // post-layer h
__device__ float g_ssrc[NTOT * NHEADS];
__device__ float g_sdst[NTOT * NHEADS];
__device__ float g_sedg[NEDGES * NHEADS];
__device__ __nv_bfloat16 g_mb[NEDGES * DMODEL]; // bf16 edge messages for stage2 gathers
__device__ int   g_edge_mem[NEDGES * MAXDEG];
__device__ int   g_edge_cnt[NEDGES];
__device__ int   g_node_edges[NTOT * MAXDEG];
__device__ int   g_node_cnt[NTOT];

// ---------------- helpers ----------------
__device__ __forceinline__ float wsum(float v) {
#pragma unroll
    for (int o = 16; o; o >>= 1) v += __shfl_xor_sync(0xffffffffu, v, o);
    return v;
}
__device__ __forceinline__ float lrelu(float x) { return x >= 0.f ? x : 0.2f * x; }

__device__ __forceinline__ float2 bf2_to_f2(unsigned u) {
    float2 r;
    r.x = __uint_as_float(u << 16);
    r.y = __uint_as_float(u & 0xffff0000u);
    return r;
}

__device__ __forceinline__ void mma_bf16(float* c, const unsigned* a, const unsigned* b) {
    asm volatile(
        "mma.sync.aligned.m16n8k16.row.col.f32.bf16.bf16.f32 "
        "{%0,%1,%2,%3}, {%4,%5,%6,%7}, {%8,%9}, {%0,%1,%2,%3};\n"
        : "+f"(c[0]), "+f"(c[1]), "+f"(c[2]), "+f"(c[3])
        : "r"(a[0]), "r"(a[1]), "r"(a[2]), "r"(a[3]), "r"(b[0]), "r"(b[1]));
}

__device__ __forceinline__ void split_bf16(float v, __nv_bfloat16& hi, __nv_bfloat16& lo) {
    __nv_bfloat16 h = __float2bfloat16_rn(v);
    hi = h;
    lo = __float2bfloat16_rn(v - __bfloat162float(h));
}

// ---------------- fused adjacency build (R6): CSC blocks 0..255 + CSR blocks (rest) ---------
// Fused so the 256 long-critical-path CSC blocks hide under 8320 CSR blocks (R10 showed
// serializing them costs ~25us).
__global__ void build_kernel(const float* __restrict__ H) {
    const int tid = threadIdx.x, lane = tid & 31, wid = tid >> 5;
    if (blockIdx.x < NEDGES / 4) {
        const int e0 = blockIdx.x * 4;
        __shared__ int s_base[4];
        __shared__ int s_wcnt[8][4];
        if (tid < 4) s_base[tid] = 0;
        __syncthreads();
        for (int base = 0; base < NTOT; base += 256) {
            int n = base + tid;
            float4 v = make_float4(0.f, 0.f, 0.f, 0.f);
            if (n < NTOT) v = *(const float4*)(H + (size_t)n * NEDGES + e0);
            bool p[4] = {v.x > 0.f, v.y > 0.f, v.z > 0.f, v.w > 0.f};
            unsigned b[4];
#pragma unroll
            for (int j = 0; j < 4; j++) b[j] = __ballot_sync(0xffffffffu, p[j]);
            if (lane == 0) {
#pragma unroll
                for (int j = 0; j < 4; j++) s_wcnt[wid][j] = __popc(b[j]);
            }
            __syncthreads();
#pragma unroll
            for (int j = 0; j < 4; j++) {
                if (p[j]) {
                    int woff = 0;
                    for (int w = 0; w < wid; w++) woff += s_wcnt[w][j];
                    int pos = s_base[j] + woff + __popc(b[j] & ((1u << lane) - 1u));
                    if (pos < MAXDEG) g_edge_mem[(size_t)(e0 + j) * MAXDEG + pos] = n;
                }
            }
            __syncthreads();
            if (tid < 4) {
                int tot = 0;
                for (int w = 0; w < 8; w++) tot += s_wcnt[w][tid];
                s_base[tid] += tot;
            }
            __syncthreads();
        }
        if (tid < 4) g_edge_cnt[e0 + tid] = s_base[tid] < MAXDEG ? s_base[tid] : MAXDEG;
    } else {
        const int n = blockIdx.x - NEDGES / 4;
        const float* row = H + (size_t)n * NEDGES;
        __shared__ int s_base;
        __shared__ int s_wcnt[8];
        if (tid == 0) s_base = 0;
        __syncthreads();
        for (int base = 0; base < NEDGES; base += 256) {
            int e = base + tid;
            bool p = row[e] > 0.f;
            unsigned b = __ballot_sync(0xffffffffu, p);
            if (lane == 0) s_wcnt[wid] = __popc(b);
            __syncthreads();
            int woff = 0;
            for (int w = 0; w < wid; w++) woff += s_wcnt[w];
            if (p) {
                int pos = s_base + woff + __popc(b & ((1u << lane) - 1u));
                g_node_edges[(size_t)n * MAXDEG + pos] = e;
            }
            __syncthreads();
            if (tid == 0) {
                int tot = 0;
                for (int w = 0; w < 8; w++) tot += s_wcnt[w];
                s_base += tot;
            }
            __syncthreads();
        }
        if (tid == 0) g_node_cnt[n] = s_base;
    }
}

// ---------------- tensor-core GEMM (split-bf16, register-prefetch pipelined) ----------------
// BM=128, BN=128, BK=32. Loads for tile kt+1 are issued into registers BEFORE computing
// tile kt from smem, overlapping global latency with mma work. Arithmetic identical to R6.
template <int KDIM, bool FIRST>
__global__ __launch_bounds__(256) void gemm_tc_kernel(
    const float* __restrict__ A, const float* __restrict__ RO,
    const float* __restrict__ W, const float* __restrict__ nemb,
    const int* __restrict__ ntype,
    const float* __restrict__ asrc, const float* __restrict__ adst) {
    constexpr int SA = 36;
    __shared__ __nv_bfloat16 sAhi[128 * SA];
    __shared__ __nv_bfloat16 sAlo[128 * SA];
    __shared__ __nv_bfloat16 sBhi[128 * SA];  // n-major: [n][k]
    __shared__ __nv_bfloat16 sBlo[128 * SA];

    const int m0 = blockIdx.x * 128, n0 = blockIdx.y * 128;
    const int tid = threadIdx.x, lane = tid & 31, warp = tid >> 5;
    const int g = lane >> 2, tg = lane & 3;
    const int wm = warp & 3, wn = warp >> 2;
    const float* Asrc = FIRST ? A : g_hB;

    // loader indices (constant per thread)
    int la_r[4], la_kc[4], lb_k[4], lb_nq[4];
#pragma unroll
    for (int i = 0; i < 4; i++) {
        int idx = tid + i * 256;
        la_r[i] = idx >> 3;
        la_kc[i] = (idx & 7) * 4;
        lb_k[i] = idx >> 5;
        lb_nq[i] = (idx & 31) * 4;
    }

    float acc[2][8][4];
#pragma unroll
    for (int mt = 0; mt < 2; mt++)
#pragma unroll
        for (int nt = 0; nt < 8; nt++)
#pragma unroll
            for (int j = 0; j < 4; j++) acc[mt][nt][j] = 0.f;

    float4 pa[4], pb[4];
    // prologue: load tile 0
#pragma unroll
    for (int i = 0; i < 4; i++) {
        int grow = m0 + la_r[i];
        if (FIRST && grow >= NPATCH) pa[i] = *(const float4*)(RO + la_kc[i]);
        else pa[i] = *(const float4*)(Asrc + (size_t)grow * KDIM + la_kc[i]);
        pb[i] = *(const float4*)(W + (size_t)lb_k[i] * DMODEL + n0 + lb_nq[i]);
    }
    // store tile 0 to smem
#pragma unroll
    for (int i = 0; i < 4; i++) {
        float vv[4] = {pa[i].x, pa[i].y, pa[i].z, pa[i].w};
#pragma unroll
        for (int j = 0; j < 4; j++) {
            __nv_bfloat16 hi, lo;
            split_bf16(vv[j], hi, lo);
            sAhi[la_r[i] * SA + la_kc[i] + j] = hi;
            sAlo[la_r[i] * SA + la_kc[i] + j] = lo;
        }
        float ww[4] = {pb[i].x, pb[i].y, pb[i].z, pb[i].w};
#pragma unroll
        for (int j = 0; j < 4; j++) {
            __nv_bfloat16 hi, lo;
            split_bf16(ww[j], hi, lo);
            sBhi[(lb_nq[i] + j) * SA + lb_k[i]] = hi;
            sBlo[(lb_nq[i] + j) * SA + lb_k[i]] = lo;
        }
    }
    __syncthreads();

    const int KT = KDIM / 32;
    for (int kt = 0; kt < KT; kt++) {
        // issue next tile's global loads (in flight during compute)
        if (kt + 1 < KT) {
            const int k0 = (kt + 1) * 32;
#pragma unroll
            for (int i = 0; i < 4; i++) {
                int grow = m0 + la_r[i];
                if (FIRST && grow >= NPATCH) pa[i] = *(const float4*)(RO + k0 + la_kc[i]);
                else pa[i] = *(const float4*)(Asrc + (size_t)grow * KDIM + k0 + la_kc[i]);
                pb[i] = *(const float4*)(W + (size_t)(k0 + lb_k[i]) * DMODEL + n0 + lb_nq[i]);
            }
        }

#pragma unroll
        for (int ks = 0; ks < 2; ks++) {
            const int kb = ks * 16;
            unsigned ahi[2][4], alo[2][4];
#pragma unroll
            for (int mt = 0; mt < 2; mt++) {
                int r0 = wm * 32 + mt * 16 + g;
                ahi[mt][0] = *(const unsigned*)&sAhi[r0 * SA + kb + 2 * tg];
                ahi[mt][1] = *(const unsigned*)&sAhi[(r0 + 8) * SA + kb + 2 * tg];
                ahi[mt][2] = *(const unsigned*)&sAhi[r0 * SA + kb + 2 * tg + 8];
                ahi[mt][3] = *(const unsigned*)&sAhi[(r0 + 8) * SA + kb + 2 * tg + 8];
                alo[mt][0] = *(const unsigned*)&sAlo[r0 * SA + kb + 2 * tg];
                alo[mt][1] = *(const unsigned*)&sAlo[(r0 + 8) * SA + kb + 2 * tg];
                alo[mt][2] = *(const unsigned*)&sAlo[r0 * SA + kb + 2 * tg + 8];
                alo[mt][3] = *(const unsigned*)&sAlo[(r0 + 8) * SA + kb + 2 * tg + 8];
            }
#pragma unroll
            for (int nt = 0; nt < 8; nt++) {
                int n = wn * 64 + nt * 8 + g;
                unsigned bhi[2], blo[2];
                bhi[0] = *(const unsigned*)&sBhi[n * SA + kb + 2 * tg];
                bhi[1] = *(const unsigned*)&sBhi[n * SA + kb + 2 * tg + 8];
                blo[0] = *(const unsigned*)&sBlo[n * SA + kb + 2 * tg];
                blo[1] = *(const unsigned*)&sBlo[n * SA + kb + 2 * tg + 8];
#pragma unroll
                for (int mt = 0; mt < 2; mt++) {
                    mma_bf16(acc[mt][nt], alo[mt], bhi);
                    mma_bf16(acc[mt][nt], ahi[mt], blo);
                    mma_bf16(acc[mt][nt], ahi[mt], bhi);
                }
            }
        }
        __syncthreads();   // smem reads done before overwrite

        if (kt + 1 < KT) {
#pragma unroll
            for (int i = 0; i < 4; i++) {
                float vv[4] = {pa[i].x, pa[i].y, pa[i].z, pa[i].w};
#pragma unroll
                for (int j = 0; j < 4; j++) {
                    __nv_bfloat16 hi, lo;
                    split_bf16(vv[j], hi, lo);
                    sAhi[la_r[i] * SA + la_kc[i] + j] = hi;
                    sAlo[la_r[i] * SA + la_kc[i] + j] = lo;
                }
                float ww[4] = {pb[i].x, pb[i].y, pb[i].z, pb[i].w};
#pragma unroll
                for (int j = 0; j < 4; j++) {
                    __nv_bfloat16 hi, lo;
                    split_bf16(ww[j], hi, lo);
                    sBhi[(lb_nq[i] + j) * SA + lb_k[i]] = hi;
                    sBlo[(lb_nq[i] + j) * SA + lb_k[i]] = lo;
                }
            }
            __syncthreads();
        }
    }

    const int h = 2 * blockIdx.y + wn;
#pragma unroll
    for (int mt = 0; mt < 2; mt++) {
        int r_a = m0 + wm * 32 + mt * 16 + g;
        int r_b = r_a + 8;
        int ta = ntype[r_a], tb = ntype[r_b];
        float ssa = 0.f, ssb = 0.f, sda = 0.f, sdb = 0.f;
#pragma unroll
        for (int nt = 0; nt < 8; nt++) {
            int c = n0 + wn * 64 + nt * 8 + 2 * tg;
            int d = nt * 8 + 2 * tg;
            float v0 = acc[mt][nt][0] + nemb[ta * DMODEL + c];
            float v1 = acc[mt][nt][1] + nemb[ta * DMODEL + c + 1];
            float v2 = acc[mt][nt][2] + nemb[tb * DMODEL + c];
            float v3 = acc[mt][nt][3] + nemb[tb * DMODEL + c + 1];
            *(float2*)&g_hA[(size_t)r_a * DMODEL + c] = make_float2(v0, v1);
            *(float2*)&g_hA[(size_t)r_b * DMODEL + c] = make_float2(v2, v3);
            __nv_bfloat162 ba, bb;
            ba.x = __float2bfloat16_rn(v0); ba.y = __float2bfloat16_rn(v1);
            bb.x = __float2bfloat16_rn(v2); bb.y = __float2bfloat16_rn(v3);
            *(__nv_bfloat162*)&g_hAb[(size_t)r_a * DMODEL + c] = ba;
            *(__nv_bfloat162*)&g_hAb[(size_t)r_b * DMODEL + c] = bb;
            float as0 = asrc[h * DHEAD + d], as1 = asrc[h * DHEAD + d + 1];
            float ad0 = adst[h * DHEAD + d], ad1 = adst[h * DHEAD + d + 1];
            ssa += v0 * as0 + v1 * as1;
            ssb += v2 * as0 + v3 * as1;
            sda += v0 * ad0 + v1 * ad1;
            sdb += v2 * ad0 + v3 * ad1;
        }
#pragma unroll
        for (int o = 1; o <= 2; o <<= 1) {
            ssa += __shfl_xor_sync(0xffffffffu, ssa, o);
            ssb += __shfl_xor_sync(0xffffffffu, ssb, o);
            sda += __shfl_xor_sync(0xffffffffu, sda, o);
            sdb += __shfl_xor_sync(0xffffffffu, sdb, o);
        }
        if (tg == 0) {
            g_ssrc[r_a * NHEADS + h] = ssa;
            g_ssrc[r_b * NHEADS + h] = ssb;
            g_sdst[r_a * NHEADS + h] = sda;
            g_sdst[r_b * NHEADS + h] = sdb;
        }
    }
}

// ---------------- stage 1: node -> edge, single-pass, 8 cols/thread (R6, measured 26us) -----
__global__ void stage1_kernel(const float* __restrict__ ebias, const int* __restrict__ etype,
                              const float* __restrict__ aedg) {
    const int e = blockIdx.x;
    const int tid = threadIdx.x, lane = tid & 31, wid = tid >> 5;
    const int cnt = g_edge_cnt[e];
    __shared__ float s_eb[4], s_inv[4];
    __shared__ float s_red[8][4];
    __shared__ uint2 s_pairs[4 * 256];
    __shared__ float s_part[8 * 256];
    if (tid < 4) s_eb[tid] = ebias[etype[e] * 4 + tid];
    __syncthreads();
    const int* mem = g_edge_mem + (size_t)e * MAXDEG;

    const int o = tid & 31;
    const int slice = tid >> 5;
    const int hq = o >> 3;
    const uint4* basep = (const uint4*)g_hAb + o;
    float a0 = 0.f, a1 = 0.f, a2 = 0.f, a3 = 0.f, a4 = 0.f, a5 = 0.f, a6 = 0.f, a7 = 0.f;
    float w0 = 0.f, w1 = 0.f, w2 = 0.f, w3 = 0.f;

    for (int base = 0; base < cnt; base += 256) {
        int i = base + tid;
        if (i < cnt) {
            int n = mem[i];
            unsigned off = (unsigned)n * (DMODEL / 8);
            float4 ss = *(const float4*)(g_ssrc + n * 4);
            float e0 = __expf(lrelu(ss.x + s_eb[0]));
            float e1 = __expf(lrelu(ss.y + s_eb[1]));
            float e2 = __expf(lrelu(ss.z + s_eb[2]));
            float e3 = __expf(lrelu(ss.w + s_eb[3]));
            s_pairs[0 * 256 + tid] = make_uint2(off, __float_as_uint(e0));
            s_pairs[1 * 256 + tid] = make_uint2(off, __float_as_uint(e1));
            s_pairs[2 * 256 + tid] = make_uint2(off, __float_as_uint(e2));
            s_pairs[3 * 256 + tid] = make_uint2(off, __float_as_uint(e3));
            w0 += e0; w1 += e1; w2 += e2; w3 += e3;
        }
        __syncthreads();
        int lim = min(256, cnt - base);
#pragma unroll 4
        for (int j = slice; j < lim; j += 8) {
            uint2 pw = s_pairs[hq * 256 + j];
            float a = __uint_as_float(pw.y);
            uint4 u = basep[pw.x];
            float2 c0 = bf2_to_f2(u.x), c1 = bf2_to_f2(u.y);
            float2 c2 = bf2_to_f2(u.z), c3 = bf2_to_f2(u.w);
            a0 += a * c0.x; a1 += a * c0.y; a2 += a * c1.x; a3 += a * c1.y;
            a4 += a * c2.x; a5 += a * c2.y; a6 += a * c3.x; a7 += a * c3.y;
        }
        __syncthreads();
    }

    w0 = wsum(w0); w1 = wsum(w1); w2 = wsum(w2); w3 = wsum(w3);
    if (lane == 0) { s_red[wid][0] = w0; s_red[wid][1] = w1; s_red[wid][2] = w2; s_red[wid][3] = w3; }
    float* pp = s_part + slice * 256 + o * 8;
    pp[0] = a0; pp[1] = a1; pp[2] = a2; pp[3] = a3;
    pp[4] = a4; pp[5] = a5; pp[6] = a6; pp[7] = a7;
    __syncthreads();
    if (tid < 4) {
        float t = 0.f;
        for (int w = 0; w < 8; w++) t += s_red[w][tid];
        s_inv[tid] = 1.f / t;
    }
    __syncthreads();
    const int c = tid;
    float m_c = 0.f;
#pragma unroll
    for (int s = 0; s < 8; s++) m_c += s_part[s * 256 + c];
    m_c *= s_inv[c >> 6];
    g_mb[(size_t)e * DMODEL + c] = __float2bfloat16_rn(m_c);

    float se = m_c * aedg[c];
    se = wsum(se);
    if (lane == 0) s_red[wid][0] = se;
    __syncthreads();
    if (tid < 4) g_sedg[e * 4 + tid] = s_red[2 * tid][0] + s_red[2 * tid + 1][0];
}

// ---------------- stage 2: edge -> node (R6, measured 40us) + optional fused LayerNorm ------
template <bool LAST>
__global__ void stage2_kernel(const float* __restrict__ ng, const float* __restrict__ nb,
                              const float* __restrict__ bg, const float* __restrict__ bb,
                              float* __restrict__ out) {
    const int n = blockIdx.x;
    const int tid = threadIdx.x, lane = tid & 31, wid = tid >> 5;
    const int cnt = g_node_cnt[n];
    __shared__ float s_sd[4], s_inv[4];
    __shared__ float s_red[8][4];
    __shared__ uint2 s_pairs[4 * 256];
    __shared__ float s_part[8 * 256];
    if (tid < 4) s_sd[tid] = g_sdst[n * 4 + tid];
    __syncthreads();
    const int* el = g_node_edges + (size_t)n * MAXDEG;

    const int o = tid & 31;
    const int slice = tid >> 5;
    const int hq = o >> 3;
    const uint4* basep = (const uint4*)g_mb + o;
    float a0 = 0.f, a1 = 0.f, a2 = 0.f, a3 = 0.f, a4 = 0.f, a5 = 0.f, a6 = 0.f, a7 = 0.f;
    float w0 = 0.f, w1 = 0.f, w2 = 0.f, w3 = 0.f;

    for (int base = 0; base < cnt; base += 256) {
        int i = base + tid;
        if (i < cnt) {
            int e = el[i];
            unsigned off = (unsigned)e * (DMODEL / 8);
            float4 sg = *(const float4*)(g_sedg + e * 4);
            float e0 = __expf(lrelu(s_sd[0] + sg.x));
            float e1 = __expf(lrelu(s_sd[1] + sg.y));
            float e2 = __expf(lrelu(s_sd[2] + sg.z));
            float e3 = __expf(lrelu(s_sd[3] + sg.w));
            s_pairs[0 * 256 + tid] = make_uint2(off, __float_as_uint(e0));
            s_pairs[1 * 256 + tid] = make_uint2(off, __float_as_uint(e1));
            s_pairs[2 * 256 + tid] = make_uint2(off, __float_as_uint(e2));
            s_pairs[3 * 256 + tid] = make_uint2(off, __float_as_uint(e3));
            w0 += e0; w1 += e1; w2 += e2; w3 += e3;
        }
        __syncthreads();
        int lim = min(256, cnt - base);
#pragma unroll 4
        for (int j = slice; j < lim; j += 8) {
            uint2 pw = s_pairs[hq * 256 + j];
            float b = __uint_as_float(pw.y);
            uint4 u = basep[pw.x];
            float2 c0 = bf2_to_f2(u.x), c1 = bf2_to_f2(u.y);
            float2 c2 = bf2_to_f2(u.z), c3 = bf2_to_f2(u.w);
            a0 += b * c0.x; a1 += b * c0.y; a2 += b * c1.x; a3 += b * c1.y;
            a4 += b * c2.x; a5 += b * c2.y; a6 += b * c3.x; a7 += b * c3.y;
        }
        __syncthreads();
    }

    w0 = wsum(w0); w1 = wsum(w1); w2 = wsum(w2); w3 = wsum(w3);
    if (lane == 0) { s_red[wid][0] = w0; s_red[wid][1] = w1; s_red[wid][2] = w2; s_red[wid][3] = w3; }
    float* pp = s_part + slice * 256 + o * 8;
    pp[0] = a0; pp[1] = a1; pp[2] = a2; pp[3] = a3;
    pp[4] = a4; pp[5] = a5; pp[6] = a6; pp[7] = a7;
    __syncthreads();
    if (tid < 4) {
        float t = 0.f;
        for (int w = 0; w < 8; w++) t += s_red[w][tid];
        s_inv[tid] = 1.f / t;
    }
    __syncthreads();
    const int c = tid;
    float acc = 0.f;
#pragma unroll
    for (int s = 0; s < 8; s++) acc += s_part[s * 256 + c];
    acc *= s_inv[c >> 6];
    float o2 = acc > 0.f ? acc : (__expf(acc) - 1.f);       // ELU(alpha=1)
    float x = o2 + g_hA[(size_t)n * DMODEL + c];

    if (!LAST) {
        g_hB[(size_t)n * DMODEL + c] = x;
    } else {
        __shared__ float sred[8];
        __shared__ float s_mean, s_rstd;
        float s = wsum(x);
        if (lane == 0) sred[wid] = s;
        __syncthreads();
        if (tid == 0) {
            float t = 0.f;
            for (int w = 0; w < 8; w++) t += sred[w];
            s_mean = t * (1.f / DMODEL);
        }
        __syncthreads();
        float cc = x - s_mean;
        float v = wsum(cc * cc);
        if (lane == 0) sred[wid] = v;
        __syncthreads();
        if (tid == 0) {
            float t = 0.f;
            for (int w = 0; w < 8; w++) t += sred[w];
            s_rstd = rsqrtf(t * (1.f / DMODEL) + 1e-5f);
        }
        __syncthreads();
        const float* gg = (n < NPATCH) ? ng : bg;
        const float* bbp = (n < NPATCH) ? nb : bb;
        out[(size_t)n * DMODEL + c] = cc * s_rstd * gg[c] + bbp[c];
    }
}

// ---------------- launcher ----------------
extern "C" void kernel_launch(void* const* d_in, const int* in_sizes, int n_in,
                              void* d_out, int out_size) {
    const float* x_nodes = (const float*)d_in[0];
    const float* ro      = (const float*)d_in[1];
    const int*   ntype   = (const int*)d_in[2];
    const int*   etype   = (const int*)d_in[3];
    const float* H       = (const float*)d_in[4];
    // d_in[5] readout_node_ids == arange(8192, 8320)
    const float* W0      = (const float*)d_in[6];
    const float* W1      = (const float*)d_in[7];
    const float* nemb    = (const float*)d_in[8];
    const float* asrc    = (const float*)d_in[9];
    const float* adst    = (const float*)d_in[10];
    const float* aedg    = (const float*)d_in[11];
    const float* ebias   = (const float*)d_in[12];
    const float* ngam    = (const float*)d_in[13];
    const float* nbet    = (const float*)d_in[14];
    const float* bgam    = (const float*)d_in[15];
    const float* bbet    = (const float*)d_in[16];
    float* out = (float*)d_out;

    build_kernel<<<NEDGES / 4 + NTOT, 256>>>(H);                                // #0
    gemm_tc_kernel<INDIM, true><<<dim3(NTOT / 128, DMODEL / 128), 256>>>(
        x_nodes, ro, W0, nemb + 0 * 4 * DMODEL, ntype, asrc, adst);             // #1
    stage1_kernel<<<NEDGES, 256>>>(ebias, etype, aedg);                         // #2
    stage2_kernel<false><<<NTOT, 256>>>(nullptr, nullptr, nullptr, nullptr, nullptr); // #3 (profiled)

    gemm_tc_kernel<DMODEL, false><<<dim3(NTOT / 128, DMODEL / 128), 256>>>(
        nullptr, nullptr, W1, nemb + 1 * 4 * DMODEL, ntype,
        asrc + NHEADS * DHEAD, adst + NHEADS * DHEAD);                          // #4
    stage1_kernel<<<NEDGES, 256>>>(ebias + 3 * NHEADS, etype, aedg + NHEADS * DHEAD); // #5
    stage2_kernel<true><<<NTOT, 256>>>(ngam, nbet, bgam, bbet, out);            // #6
}